// round 3
// baseline (speedup 1.0000x reference)
#include <cuda_runtime.h>

// TemporalGCN: B=32, T=512, C=22, FREQ=192, HID=128
// out[b,t,h] = mean_c relu( b1[h] + sum_j A[c,j] * y2[j,h] )
//   y2 = relu( b0 + A @ (x @ W0^T) ) @ W1^T     (A-mix commutes with the linear map)
//
// One block per (b,t). 256 threads. Fully fp32.

#define CC   22
#define FF   192
#define HH   128
#define NBT  (32*512)
#define NTHR 256

// smem layout (floats), unioned to stay under the 48KB static limit:
//   sA   : 484            [0, 484)
//   sB1  : 4224  (x, later y2)          [484, 4708)
//   sW   : 128*36 = 4608  (weight tile; later sRed)  [4708, 9316)
//   sY   : 22*128 = 2816  (y, later y3) [9316, 12132)
#define OFF_A   0
#define OFF_B1  484
#define OFF_W   4708
#define OFF_Y   9316
#define SMEM_FLOATS 12132

__global__ __launch_bounds__(NTHR) void tgcn_kernel(
    const float* __restrict__ x,  const float* __restrict__ A,
    const float* __restrict__ W0, const float* __restrict__ b0,
    const float* __restrict__ W1, const float* __restrict__ b1,
    float* __restrict__ out)
{
    __shared__ float smem[SMEM_FLOATS];
    float* sA  = smem + OFF_A;
    float* sB1 = smem + OFF_B1;   // x, then y2
    float* sW  = smem + OFF_W;    // weight tile (padded rows of 36), then sRed
    float* sY  = smem + OFF_Y;    // y, then y3

    const int bt = blockIdx.x;
    const int t  = threadIdx.x;
    const int w  = t >> 5, l = t & 31;
    const int h  = ((w & 3) << 5) + l;   // 0..127
    const int chalf = w >> 2;            // 0 or 1
    const int cbase = chalf * 11;        // c rows 0..10 or 11..21

    // ---- Stage x [22,192] and A [22,22] into smem ----
    {
        const float4* xg  = reinterpret_cast<const float4*>(x + (size_t)bt * (CC*FF));
        float4*       sX4 = reinterpret_cast<float4*>(sB1);
        for (int i = t; i < CC*FF/4; i += NTHR) sX4[i] = xg[i];
        const float* Ag = A + (size_t)bt * (CC*CC);
        for (int i = t; i < CC*CC; i += NTHR) sA[i] = Ag[i];
    }
    __syncthreads();

    float acc[11];

    // ==== Phase A: y[c,h] = sum_f x[c,f] * W0[h,f]   (K=192, 6 tiles of 32) ====
    #pragma unroll
    for (int c = 0; c < 11; c++) acc[c] = 0.f;
    {
        const float4* sX4 = reinterpret_cast<const float4*>(sB1);
        for (int ft = 0; ft < FF/32; ft++) {
            const int f0 = ft * 32;
            // cooperative load of W0 tile [128h x 32f] -> sW[h*36 + f]
            #pragma unroll
            for (int i = 0; i < 4; i++) {
                int linear = t + NTHR*i;     // 0..1023
                int hh = linear >> 3;        // 0..127
                int fq = linear & 7;         // 0..7
                float4 v = *reinterpret_cast<const float4*>(W0 + hh*FF + f0 + fq*4);
                *reinterpret_cast<float4*>(&sW[hh*36 + fq*4]) = v;
            }
            __syncthreads();
            const float4* sWrow = reinterpret_cast<const float4*>(&sW[h*36]);
            #pragma unroll
            for (int f4 = 0; f4 < 8; f4++) {
                float4 wv = sWrow[f4];
                #pragma unroll
                for (int c = 0; c < 11; c++) {
                    float4 xv = sX4[(cbase + c)*(FF/4) + ft*8 + f4];
                    acc[c] += wv.x*xv.x + wv.y*xv.y + wv.z*xv.z + wv.w*xv.w;
                }
            }
            __syncthreads();
        }
    }
    #pragma unroll
    for (int c = 0; c < 11; c++) sY[(cbase + c)*HH + h] = acc[c];
    __syncthreads();

    // ==== Phase B: y2[c,h] = relu( b0[h] + sum_j A[c,j] * y[j,h] ) ====
    {
        const float bb = b0[h];
        #pragma unroll
        for (int c = 0; c < 11; c++) acc[c] = bb;
        for (int j = 0; j < CC; j++) {
            float yv = sY[j*HH + h];
            #pragma unroll
            for (int c = 0; c < 11; c++)
                acc[c] += sA[(cbase + c)*CC + j] * yv;
        }
    }
    __syncthreads();   // all reads of sB1-as-x are long done; reuse it for y2
    #pragma unroll
    for (int c = 0; c < 11; c++) sB1[(cbase + c)*HH + h] = fmaxf(acc[c], 0.f);
    __syncthreads();

    // ==== Phase C: y3[c,h] = sum_f y2[c,f] * W1[h,f]   (K=128, 4 tiles of 32) ====
    #pragma unroll
    for (int c = 0; c < 11; c++) acc[c] = 0.f;
    {
        const float4* sY24 = reinterpret_cast<const float4*>(sB1);
        for (int ft = 0; ft < HH/32; ft++) {
            const int f0 = ft * 32;
            #pragma unroll
            for (int i = 0; i < 4; i++) {
                int linear = t + NTHR*i;
                int hh = linear >> 3;
                int fq = linear & 7;
                float4 v = *reinterpret_cast<const float4*>(W1 + hh*HH + f0 + fq*4);
                *reinterpret_cast<float4*>(&sW[hh*36 + fq*4]) = v;
            }
            __syncthreads();
            const float4* sWrow = reinterpret_cast<const float4*>(&sW[h*36]);
            #pragma unroll
            for (int f4 = 0; f4 < 8; f4++) {
                float4 wv = sWrow[f4];
                #pragma unroll
                for (int c = 0; c < 11; c++) {
                    float4 xv = sY24[(cbase + c)*(HH/4) + ft*8 + f4];
                    acc[c] += wv.x*xv.x + wv.y*xv.y + wv.z*xv.z + wv.w*xv.w;
                }
            }
            __syncthreads();
        }
    }
    #pragma unroll
    for (int c = 0; c < 11; c++) sY[(cbase + c)*HH + h] = acc[c];
    __syncthreads();

    // ==== Phase D: out[h] = (1/22) * sum_c relu( b1[h] + sum_j A[c,j]*y3[j,h] ) ====
    {
        const float bb = b1[h];
        #pragma unroll
        for (int c = 0; c < 11; c++) acc[c] = bb;
        for (int j = 0; j < CC; j++) {
            float yv = sY[j*HH + h];
            #pragma unroll
            for (int c = 0; c < 11; c++)
                acc[c] += sA[(cbase + c)*CC + j] * yv;
        }
        float part = 0.f;
        #pragma unroll
        for (int c = 0; c < 11; c++) part += fmaxf(acc[c], 0.f);
        // sW region is dead (last read before the preceding barrier): use as reduction pad
        float* sRed = sW;
        sRed[chalf*HH + h] = part;
        __syncthreads();
        if (t < HH)
            out[(size_t)bt*HH + t] = (sRed[t] + sRed[HH + t]) * (1.f/22.f);
    }
}

extern "C" void kernel_launch(void* const* d_in, const int* in_sizes, int n_in,
                              void* d_out, int out_size) {
    const float* x  = (const float*)d_in[0];   // [32,512,22,192]
    const float* A  = (const float*)d_in[1];   // [32,512,22,22]
    const float* W0 = (const float*)d_in[2];   // [128,192]
    const float* b0 = (const float*)d_in[3];   // [128]
    const float* W1 = (const float*)d_in[4];   // [128,128]
    const float* b1 = (const float*)d_in[5];   // [128]
    float* out = (float*)d_out;                // [32,512,128]

    tgcn_kernel<<<NBT, NTHR>>>(x, A, W0, b0, W1, b1, out);
}

// round 4
// speedup vs baseline: 2.1626x; 2.1626x over previous
#include <cuda_runtime.h>

// TemporalGCN: B=32, T=512, C=22, FREQ=192, HID=128
// out[b,t,h] = mean_c relu( b1[h] + sum_j A[c,j] * y3[j,h] )
//   y3 = relu( b0 + A @ (x @ W0^T) ) @ W1^T   (A-mix commutes with the linear map)
//
// One block per (b,t). 128 threads, each owning 2 h-columns x 11 c-rows.

#define CC    22
#define CCP   24          // padded C for float4 A-mix
#define FF    192
#define HH    128
#define NBT   (32*512)
#define NTHR  128

// smem layout (floats), all region bases 16B-aligned:
//   sA  : 22*24 = 528   (row stride 24, j=22,23 zeroed)
//   sB1 : 22*192 = 4224 (x, later y2)
//   sW  : 128*32 = 4096 (XOR-swizzled weight tile; later reduction pad)
//   sY  : 24*128 = 3072 (y / y3, rows 22,23 zeroed)
#define OFF_A   0
#define OFF_B1  528
#define OFF_W   (528 + 4224)
#define OFF_Y   (528 + 4224 + 4096)
#define SMEM_FLOATS (528 + 4224 + 4096 + 3072)   // 11920 floats = 47680 B

__global__ __launch_bounds__(NTHR, 4) void tgcn_kernel(
    const float* __restrict__ x,  const float* __restrict__ A,
    const float* __restrict__ W0, const float* __restrict__ b0,
    const float* __restrict__ W1, const float* __restrict__ b1,
    float* __restrict__ out)
{
    __shared__ float smem[SMEM_FLOATS];
    float*  sA  = smem + OFF_A;
    float*  sB1 = smem + OFF_B1;                         // x, then y2
    float4* sW4 = reinterpret_cast<float4*>(smem + OFF_W);
    float*  sY  = smem + OFF_Y;

    const int bt = blockIdx.x;
    const int t  = threadIdx.x;
    const int w  = t >> 5, l = t & 31;
    const int h0 = ((w & 1) << 5) + l;    // 0..63
    const int h1 = h0 + 64;               // 64..127
    const int chalf = w >> 1;             // 0 or 1
    const int cbase = chalf * 11;

    // ---- Stage x [22,192], A [22,22]->[22,24], zero pads ----
    {
        const float4* xg  = reinterpret_cast<const float4*>(x + (size_t)bt * (CC*FF));
        float4*       sX4 = reinterpret_cast<float4*>(sB1);
        #pragma unroll
        for (int i = t; i < CC*FF/4; i += NTHR) sX4[i] = xg[i];
        const float* Ag = A + (size_t)bt * (CC*CC);
        for (int i = t; i < CC*CC; i += NTHR) {
            int c = i / CC, j = i - c*CC;
            sA[c*CCP + j] = Ag[i];
        }
        if (t < 44) sA[(t >> 1)*CCP + CC + (t & 1)] = 0.f;   // A pad cols
        sY[22*HH + t] = 0.f;                                  // sY pad rows
        sY[23*HH + t] = 0.f;
    }
    __syncthreads();

    float acc0[11], acc1[11];

    // ==== Phase A: y[c,h] = sum_f x[c,f] * W0[h,f]  (6 K-tiles of 32) ====
    #pragma unroll
    for (int c = 0; c < 11; c++) { acc0[c] = 0.f; acc1[c] = 0.f; }
    {
        const float4* sX4 = reinterpret_cast<const float4*>(sB1);
        for (int ft = 0; ft < FF/32; ft++) {
            #pragma unroll
            for (int i = 0; i < 8; i++) {                 // W0 tile [128h x 32f]
                int linear = t + NTHR*i;                  // 0..1023
                int hh = linear >> 3, fq = linear & 7;
                float4 v = *reinterpret_cast<const float4*>(W0 + hh*FF + ft*32 + fq*4);
                sW4[hh*8 + (fq ^ (hh & 7))] = v;          // XOR-swizzle, conflict-free
            }
            __syncthreads();
            #pragma unroll
            for (int f4 = 0; f4 < 8; f4++) {
                float4 wv0 = sW4[h0*8 + (f4 ^ (h0 & 7))];
                float4 wv1 = sW4[h1*8 + (f4 ^ (h1 & 7))];
                #pragma unroll
                for (int c = 0; c < 11; c++) {
                    float4 xv = sX4[(cbase + c)*(FF/4) + ft*8 + f4];
                    acc0[c] += wv0.x*xv.x + wv0.y*xv.y + wv0.z*xv.z + wv0.w*xv.w;
                    acc1[c] += wv1.x*xv.x + wv1.y*xv.y + wv1.z*xv.z + wv1.w*xv.w;
                }
            }
            __syncthreads();
        }
    }
    #pragma unroll
    for (int c = 0; c < 11; c++) {
        sY[(cbase + c)*HH + h0] = acc0[c];
        sY[(cbase + c)*HH + h1] = acc1[c];
    }
    __syncthreads();

    // ==== Phase B: y2[c,h] = relu(b0[h] + sum_j A[c,j]*y[j,h])  (j in groups of 4) ====
    {
        const float bb0 = b0[h0], bb1 = b0[h1];
        #pragma unroll
        for (int c = 0; c < 11; c++) { acc0[c] = bb0; acc1[c] = bb1; }
        const float4* sA4 = reinterpret_cast<const float4*>(sA);
        #pragma unroll
        for (int jg = 0; jg < CCP/4; jg++) {
            float yv0[4], yv1[4];
            #pragma unroll
            for (int q = 0; q < 4; q++) {
                yv0[q] = sY[(jg*4 + q)*HH + h0];
                yv1[q] = sY[(jg*4 + q)*HH + h1];
            }
            #pragma unroll
            for (int c = 0; c < 11; c++) {
                float4 av = sA4[(cbase + c)*(CCP/4) + jg];
                acc0[c] += av.x*yv0[0] + av.y*yv0[1] + av.z*yv0[2] + av.w*yv0[3];
                acc1[c] += av.x*yv1[0] + av.y*yv1[1] + av.z*yv1[2] + av.w*yv1[3];
            }
        }
    }
    __syncthreads();                      // x reads done; sB1 becomes y2
    #pragma unroll
    for (int c = 0; c < 11; c++) {
        sB1[(cbase + c)*HH + h0] = fmaxf(acc0[c], 0.f);
        sB1[(cbase + c)*HH + h1] = fmaxf(acc1[c], 0.f);
    }
    __syncthreads();

    // ==== Phase C: y3[c,h] = sum_f y2[c,f] * W1[h,f]  (4 K-tiles of 32) ====
    #pragma unroll
    for (int c = 0; c < 11; c++) { acc0[c] = 0.f; acc1[c] = 0.f; }
    {
        const float4* sY24 = reinterpret_cast<const float4*>(sB1);
        for (int ft = 0; ft < HH/32; ft++) {
            #pragma unroll
            for (int i = 0; i < 8; i++) {                 // W1 tile [128h x 32f]
                int linear = t + NTHR*i;
                int hh = linear >> 3, fq = linear & 7;
                float4 v = *reinterpret_cast<const float4*>(W1 + hh*HH + ft*32 + fq*4);
                sW4[hh*8 + (fq ^ (hh & 7))] = v;
            }
            __syncthreads();
            #pragma unroll
            for (int f4 = 0; f4 < 8; f4++) {
                float4 wv0 = sW4[h0*8 + (f4 ^ (h0 & 7))];
                float4 wv1 = sW4[h1*8 + (f4 ^ (h1 & 7))];
                #pragma unroll
                for (int c = 0; c < 11; c++) {
                    float4 xv = sY24[(cbase + c)*(HH/4) + ft*8 + f4];
                    acc0[c] += wv0.x*xv.x + wv0.y*xv.y + wv0.z*xv.z + wv0.w*xv.w;
                    acc1[c] += wv1.x*xv.x + wv1.y*xv.y + wv1.z*xv.z + wv1.w*xv.w;
                }
            }
            __syncthreads();
        }
    }
    #pragma unroll
    for (int c = 0; c < 11; c++) {
        sY[(cbase + c)*HH + h0] = acc0[c];
        sY[(cbase + c)*HH + h1] = acc1[c];
    }
    __syncthreads();

    // ==== Phase D: out[h] = (1/22) * sum_c relu(b1[h] + sum_j A[c,j]*y3[j,h]) ====
    {
        const float bb0 = b1[h0], bb1 = b1[h1];
        #pragma unroll
        for (int c = 0; c < 11; c++) { acc0[c] = bb0; acc1[c] = bb1; }
        const float4* sA4 = reinterpret_cast<const float4*>(sA);
        #pragma unroll
        for (int jg = 0; jg < CCP/4; jg++) {
            float yv0[4], yv1[4];
            #pragma unroll
            for (int q = 0; q < 4; q++) {
                yv0[q] = sY[(jg*4 + q)*HH + h0];
                yv1[q] = sY[(jg*4 + q)*HH + h1];
            }
            #pragma unroll
            for (int c = 0; c < 11; c++) {
                float4 av = sA4[(cbase + c)*(CCP/4) + jg];
                acc0[c] += av.x*yv0[0] + av.y*yv0[1] + av.z*yv0[2] + av.w*yv0[3];
                acc1[c] += av.x*yv1[0] + av.y*yv1[1] + av.z*yv1[2] + av.w*yv1[3];
            }
        }
        float part0 = 0.f, part1 = 0.f;
        #pragma unroll
        for (int c = 0; c < 11; c++) {
            part0 += fmaxf(acc0[c], 0.f);
            part1 += fmaxf(acc1[c], 0.f);
        }
        // sW region is dead here: reuse as 2x128 reduction pad
        float* sRed = reinterpret_cast<float*>(sW4);
        sRed[chalf*HH + h0] = part0;
        sRed[chalf*HH + h1] = part1;
        __syncthreads();
        if (t < 64) {
            out[(size_t)bt*HH + h0] = (sRed[h0] + sRed[HH + h0]) * (1.f/22.f);
            out[(size_t)bt*HH + h1] = (sRed[h1] + sRed[HH + h1]) * (1.f/22.f);
        }
    }
}

extern "C" void kernel_launch(void* const* d_in, const int* in_sizes, int n_in,
                              void* d_out, int out_size) {
    const float* x  = (const float*)d_in[0];   // [32,512,22,192]
    const float* A  = (const float*)d_in[1];   // [32,512,22,22]
    const float* W0 = (const float*)d_in[2];   // [128,192]
    const float* b0 = (const float*)d_in[3];   // [128]
    const float* W1 = (const float*)d_in[4];   // [128,128]
    const float* b1 = (const float*)d_in[5];   // [128]
    float* out = (float*)d_out;                // [32,512,128]

    tgcn_kernel<<<NBT, NTHR>>>(x, A, W0, b0, W1, b1, out);
}

// round 6
// speedup vs baseline: 2.2154x; 1.0244x over previous
#include <cuda_runtime.h>
#include <cuda_bf16.h>
#include <cstdint>

// TemporalGCN  B=32,T=512,C=22,FREQ=192,HID=128  — fused per-(b,t) block.
// Phases A/C (x@W0^T, y2@W1^T) on tensor cores via mma.sync bf16x3 split.
// Phases B/D (A-mix) on CUDA cores (cheap).

#define NBT  16384
#define XS   200        // sX row stride, bf16 elems (400B, ldmatrix conflict-free)
#define Y2S  136        // sY2 row stride (272B, conflict-free)

// Pre-split weights (bf16 hi/lo), filled by prep_kernel each launch.
__device__ __nv_bfloat16 g_w0h[128*192], g_w0l[128*192];
__device__ __nv_bfloat16 g_w1h[128*128], g_w1l[128*128];

__device__ __forceinline__ uint32_t smem_u32(const void* p) {
    uint32_t a;
    asm("{ .reg .u64 t; cvta.to.shared.u64 t, %1; cvt.u32.u64 %0, t; }" : "=r"(a) : "l"(p));
    return a;
}
__device__ __forceinline__ void ldsm_x4(uint32_t* r, uint32_t addr) {
    asm volatile("ldmatrix.sync.aligned.m8n8.x4.shared.b16 {%0,%1,%2,%3}, [%4];"
        : "=r"(r[0]), "=r"(r[1]), "=r"(r[2]), "=r"(r[3]) : "r"(addr));
}
__device__ __forceinline__ void mma_bf16(float* c, const uint32_t* a, const uint32_t* b) {
    asm volatile("mma.sync.aligned.m16n8k16.row.col.f32.bf16.bf16.f32 "
        "{%0,%1,%2,%3}, {%4,%5,%6,%7}, {%8,%9}, {%0,%1,%2,%3};"
        : "+f"(c[0]), "+f"(c[1]), "+f"(c[2]), "+f"(c[3])
        : "r"(a[0]), "r"(a[1]), "r"(a[2]), "r"(a[3]), "r"(b[0]), "r"(b[1]));
}
__device__ __forceinline__ void split2(float v0, float v1, uint32_t& hw, uint32_t& lw) {
    __nv_bfloat16 h0 = __float2bfloat16(v0), h1 = __float2bfloat16(v1);
    __nv_bfloat16 l0 = __float2bfloat16(v0 - __bfloat162float(h0));
    __nv_bfloat16 l1 = __float2bfloat16(v1 - __bfloat162float(h1));
    hw = (uint32_t)__bfloat16_as_ushort(h0) | ((uint32_t)__bfloat16_as_ushort(h1) << 16);
    lw = (uint32_t)__bfloat16_as_ushort(l0) | ((uint32_t)__bfloat16_as_ushort(l1) << 16);
}

__global__ __launch_bounds__(256) void prep_kernel(const float* __restrict__ W0,
                                                   const float* __restrict__ W1) {
    int i = blockIdx.x * 256 + threadIdx.x;
    if (i < 128*192) {
        float v = W0[i];
        __nv_bfloat16 h = __float2bfloat16(v);
        g_w0h[i] = h;
        g_w0l[i] = __float2bfloat16(v - __bfloat162float(h));
    } else {
        int j = i - 128*192;
        if (j < 128*128) {
            float v = W1[j];
            __nv_bfloat16 h = __float2bfloat16(v);
            g_w1h[j] = h;
            g_w1l[j] = __float2bfloat16(v - __bfloat162float(h));
        }
    }
}

// smem byte offsets (all 16B aligned)
#define OFF_XH   0            // 32*400   = 12800
#define OFF_XL   12800        // 12800
#define OFF_Y2H  25600        // 32*272   = 8704
#define OFF_Y2L  34304        // 8704
#define OFF_SY   43008        // 24*128*4 = 12288
#define OFF_SA   55296        // 528*4    = 2112
#define OFF_RED  57408        // 256*4    = 1024
#define SMEM_BYTES 58432

__global__ __launch_bounds__(128) void fused_kernel(
    const float* __restrict__ x,  const float* __restrict__ A,
    const float* __restrict__ b0, const float* __restrict__ b1,
    float* __restrict__ out)
{
    extern __shared__ char sm[];
    float* sY   = reinterpret_cast<float*>(sm + OFF_SY);
    float* sA   = reinterpret_cast<float*>(sm + OFF_SA);
    float* sRed = reinterpret_cast<float*>(sm + OFF_RED);
    const uint32_t sbase = smem_u32(sm);

    const int bt = blockIdx.x, t = threadIdx.x;
    const int wid = t >> 5, l = t & 31;
    const int n0 = wid * 32;                    // warp's N range (32 cols)
    const int h0 = ((wid & 1) << 5) + l;        // phase B/D layout
    const int h1 = h0 + 64;
    const int chalf = wid >> 1, cbase = chalf * 11;

    // ---- Stage: x -> bf16 hi/lo (rows 0..21), A -> sA, zero sY pad rows ----
    {
        const float* xr = x + (size_t)bt * (22*192);
        for (int i = t; i < 22*24; i += 128) {          // 8-elem chunks
            int row = i / 24, cr = i - row * 24;
            const float4* g4 = reinterpret_cast<const float4*>(xr + row*192 + cr*8);
            float4 a = g4[0], b = g4[1];
            uint32_t hw[4], lw[4];
            split2(a.x, a.y, hw[0], lw[0]); split2(a.z, a.w, hw[1], lw[1]);
            split2(b.x, b.y, hw[2], lw[2]); split2(b.z, b.w, hw[3], lw[3]);
            *reinterpret_cast<uint4*>(sm + OFF_XH + row*400 + cr*16) =
                make_uint4(hw[0], hw[1], hw[2], hw[3]);
            *reinterpret_cast<uint4*>(sm + OFF_XL + row*400 + cr*16) =
                make_uint4(lw[0], lw[1], lw[2], lw[3]);
        }
        const float* Ag = A + (size_t)bt * 484;
        for (int i = t; i < 484; i += 128) { int c = i / 22; sA[c*24 + (i - c*22)] = Ag[i]; }
        if (t < 44) sA[(t >> 1)*24 + 22 + (t & 1)] = 0.f;
        sY[22*128 + t] = 0.f;                            // mean-pad rows stay zero
        sY[23*128 + t] = 0.f;
    }
    __syncthreads();

    float acc[2][4][4];
    const int aoff  = (l & 15) * 400 + (l >> 4) * 16;   // ldmatrix lane offset (phase A)
    const int aoff2 = (l & 15) * 272 + (l >> 4) * 16;   // (phase C)

    // ==== Phase A: y[c,h] = x @ W0^T  (M=22 pad 32, N=32/warp, K=192) ====
    #pragma unroll
    for (int mi = 0; mi < 2; mi++)
        #pragma unroll
        for (int tt = 0; tt < 4; tt++)
            #pragma unroll
            for (int q = 0; q < 4; q++) acc[mi][tt][q] = 0.f;

    for (int ks = 0; ks < 12; ks++) {
        uint32_t ah[2][4], al[2][4], bh[4][2], bl[4][2];
        ldsm_x4(ah[0], sbase + OFF_XH + ks*32 + aoff);
        ldsm_x4(ah[1], sbase + OFF_XH + 16*400 + ks*32 + aoff);
        ldsm_x4(al[0], sbase + OFF_XL + ks*32 + aoff);
        ldsm_x4(al[1], sbase + OFF_XL + 16*400 + ks*32 + aoff);
        const int krow = ks*16 + (l & 3)*2;
        #pragma unroll
        for (int tt = 0; tt < 4; tt++) {
            const int nr = n0 + tt*8 + (l >> 2);
            const __nv_bfloat16* p = g_w0h + nr*192 + krow;
            const __nv_bfloat16* q = g_w0l + nr*192 + krow;
            bh[tt][0] = *reinterpret_cast<const uint32_t*>(p);
            bh[tt][1] = *reinterpret_cast<const uint32_t*>(p + 8);
            bl[tt][0] = *reinterpret_cast<const uint32_t*>(q);
            bl[tt][1] = *reinterpret_cast<const uint32_t*>(q + 8);
        }
        #pragma unroll
        for (int mi = 0; mi < 2; mi++)
            #pragma unroll
            for (int tt = 0; tt < 4; tt++) mma_bf16(acc[mi][tt], ah[mi], bh[tt]);
        #pragma unroll
        for (int mi = 0; mi < 2; mi++)
            #pragma unroll
            for (int tt = 0; tt < 4; tt++) mma_bf16(acc[mi][tt], al[mi], bh[tt]);
        #pragma unroll
        for (int mi = 0; mi < 2; mi++)
            #pragma unroll
            for (int tt = 0; tt < 4; tt++) mma_bf16(acc[mi][tt], ah[mi], bl[tt]);
    }
    // epilogue -> sY (fp32), rows < 22 only
    #pragma unroll
    for (int mi = 0; mi < 2; mi++)
        #pragma unroll
        for (int tt = 0; tt < 4; tt++) {
            int r0 = mi*16 + (l >> 2), c = n0 + tt*8 + (l & 3)*2;
            if (r0 < 22)
                *reinterpret_cast<float2*>(sY + r0*128 + c) =
                    make_float2(acc[mi][tt][0], acc[mi][tt][1]);
            if (r0 + 8 < 22)
                *reinterpret_cast<float2*>(sY + (r0+8)*128 + c) =
                    make_float2(acc[mi][tt][2], acc[mi][tt][3]);
        }
    __syncthreads();

    // ==== Phase B: y2 = relu(b0 + A@y), store bf16 hi/lo for phase C ====
    {
        float a0[11], a1[11];
        const float bb0 = b0[h0], bb1 = b0[h1];
        #pragma unroll
        for (int c = 0; c < 11; c++) { a0[c] = bb0; a1[c] = bb1; }
        const float4* sA4 = reinterpret_cast<const float4*>(sA);
        #pragma unroll
        for (int jg = 0; jg < 6; jg++) {
            float yv0[4], yv1[4];
            #pragma unroll
            for (int q = 0; q < 4; q++) {
                yv0[q] = sY[(jg*4+q)*128 + h0];
                yv1[q] = sY[(jg*4+q)*128 + h1];
            }
            #pragma unroll
            for (int c = 0; c < 11; c++) {
                float4 av = sA4[(cbase + c)*6 + jg];
                a0[c] += av.x*yv0[0] + av.y*yv0[1] + av.z*yv0[2] + av.w*yv0[3];
                a1[c] += av.x*yv1[0] + av.y*yv1[1] + av.z*yv1[2] + av.w*yv1[3];
            }
        }
        __nv_bfloat16* y2h = reinterpret_cast<__nv_bfloat16*>(sm + OFF_Y2H);
        __nv_bfloat16* y2l = reinterpret_cast<__nv_bfloat16*>(sm + OFF_Y2L);
        #pragma unroll
        for (int c = 0; c < 11; c++) {
            float v0 = fmaxf(a0[c], 0.f), v1 = fmaxf(a1[c], 0.f);
            __nv_bfloat16 hh0 = __float2bfloat16(v0), hh1 = __float2bfloat16(v1);
            y2h[(cbase+c)*Y2S + h0] = hh0;
            y2l[(cbase+c)*Y2S + h0] = __float2bfloat16(v0 - __bfloat162float(hh0));
            y2h[(cbase+c)*Y2S + h1] = hh1;
            y2l[(cbase+c)*Y2S + h1] = __float2bfloat16(v1 - __bfloat162float(hh1));
        }
    }
    __syncthreads();

    // ==== Phase C: y3 = y2 @ W1^T  (K=128) ====
    #pragma unroll
    for (int mi = 0; mi < 2; mi++)
        #pragma unroll
        for (int tt = 0; tt < 4; tt++)
            #pragma unroll
            for (int q = 0; q < 4; q++) acc[mi][tt][q] = 0.f;

    for (int ks = 0; ks < 8; ks++) {
        uint32_t ah[2][4], al[2][4], bh[4][2], bl[4][2];
        ldsm_x4(ah[0], sbase + OFF_Y2H + ks*32 + aoff2);
        ldsm_x4(ah[1], sbase + OFF_Y2H + 16*272 + ks*32 + aoff2);
        ldsm_x4(al[0], sbase + OFF_Y2L + ks*32 + aoff2);
        ldsm_x4(al[1], sbase + OFF_Y2L + 16*272 + ks*32 + aoff2);
        const int krow = ks*16 + (l & 3)*2;
        #pragma unroll
        for (int tt = 0; tt < 4; tt++) {
            const int nr = n0 + tt*8 + (l >> 2);
            const __nv_bfloat16* p = g_w1h + nr*128 + krow;
            const __nv_bfloat16* q = g_w1l + nr*128 + krow;
            bh[tt][0] = *reinterpret_cast<const uint32_t*>(p);
            bh[tt][1] = *reinterpret_cast<const uint32_t*>(p + 8);
            bl[tt][0] = *reinterpret_cast<const uint32_t*>(q);
            bl[tt][1] = *reinterpret_cast<const uint32_t*>(q + 8);
        }
        #pragma unroll
        for (int mi = 0; mi < 2; mi++)
            #pragma unroll
            for (int tt = 0; tt < 4; tt++) mma_bf16(acc[mi][tt], ah[mi], bh[tt]);
        #pragma unroll
        for (int mi = 0; mi < 2; mi++)
            #pragma unroll
            for (int tt = 0; tt < 4; tt++) mma_bf16(acc[mi][tt], al[mi], bh[tt]);
        #pragma unroll
        for (int mi = 0; mi < 2; mi++)
            #pragma unroll
            for (int tt = 0; tt < 4; tt++) mma_bf16(acc[mi][tt], ah[mi], bl[tt]);
    }
    #pragma unroll
    for (int mi = 0; mi < 2; mi++)
        #pragma unroll
        for (int tt = 0; tt < 4; tt++) {
            int r0 = mi*16 + (l >> 2), c = n0 + tt*8 + (l & 3)*2;
            if (r0 < 22)
                *reinterpret_cast<float2*>(sY + r0*128 + c) =
                    make_float2(acc[mi][tt][0], acc[mi][tt][1]);
            if (r0 + 8 < 22)
                *reinterpret_cast<float2*>(sY + (r0+8)*128 + c) =
                    make_float2(acc[mi][tt][2], acc[mi][tt][3]);
        }
    __syncthreads();

    // ==== Phase D: out[h] = (1/22) * sum_c relu(b1[h] + sum_j A[c,j]*y3[j,h]) ====
    {
        float a0[11], a1[11];
        const float bb0 = b1[h0], bb1 = b1[h1];
        #pragma unroll
        for (int c = 0; c < 11; c++) { a0[c] = bb0; a1[c] = bb1; }
        const float4* sA4 = reinterpret_cast<const float4*>(sA);
        #pragma unroll
        for (int jg = 0; jg < 6; jg++) {
            float yv0[4], yv1[4];
            #pragma unroll
            for (int q = 0; q < 4; q++) {
                yv0[q] = sY[(jg*4+q)*128 + h0];
                yv1[q] = sY[(jg*4+q)*128 + h1];
            }
            #pragma unroll
            for (int c = 0; c < 11; c++) {
                float4 av = sA4[(cbase + c)*6 + jg];
                a0[c] += av.x*yv0[0] + av.y*yv0[1] + av.z*yv0[2] + av.w*yv0[3];
                a1[c] += av.x*yv1[0] + av.y*yv1[1] + av.z*yv1[2] + av.w*yv1[3];
            }
        }
        float p0 = 0.f, p1 = 0.f;
        #pragma unroll
        for (int c = 0; c < 11; c++) { p0 += fmaxf(a0[c], 0.f); p1 += fmaxf(a1[c], 0.f); }
        sRed[chalf*128 + h0] = p0;
        sRed[chalf*128 + h1] = p1;
        __syncthreads();
        if (t < 64) {
            out[(size_t)bt*128 + h0] = (sRed[h0] + sRed[128 + h0]) * (1.f/22.f);
            out[(size_t)bt*128 + h1] = (sRed[h1] + sRed[128 + h1]) * (1.f/22.f);
        }
    }
}

extern "C" void kernel_launch(void* const* d_in, const int* in_sizes, int n_in,
                              void* d_out, int out_size) {
    const float* x  = (const float*)d_in[0];   // [32,512,22,192]
    const float* A  = (const float*)d_in[1];   // [16384,22,22]
    const float* W0 = (const float*)d_in[2];   // [128,192]
    const float* b0 = (const float*)d_in[3];
    const float* W1 = (const float*)d_in[4];   // [128,128]
    const float* b1 = (const float*)d_in[5];
    float* out = (float*)d_out;                // [16384,128]

    cudaFuncSetAttribute(fused_kernel, cudaFuncAttributeMaxDynamicSharedMemorySize, SMEM_BYTES);
    prep_kernel<<<(128*192 + 128*128 + 255) / 256, 256>>>(W0, W1);
    fused_kernel<<<NBT, 128, SMEM_BYTES>>>(x, A, b0, b1, out);
}

// round 8
// speedup vs baseline: 3.5226x; 1.5900x over previous
#include <cuda_runtime.h>
#include <cuda_bf16.h>
#include <cstdint>

// TemporalGCN  B=32,T=512,C=22,FREQ=192,HID=128 — fused per-(b,t) block.
// Phases A/C on tensor cores (mma.sync bf16x3 split); W pre-permuted into
// mma-fragment order so every B-fragment load is one coalesced 128B line.

#define NBT  16384
#define Y2S  136        // sY2 row stride in bf16 elems (272B, ldmatrix conflict-free)

// W packed in fragment order: slot (((ks*4+w)*4+tt)*2+r)*32 + lane  -> uint32 (2 bf16)
#define NW0  (12*4*4*2*32)   // 12288
#define NW1  (8*4*4*2*32)    // 8192
__device__ uint32_t g_pw0h[NW0], g_pw0l[NW0];
__device__ uint32_t g_pw1h[NW1], g_pw1l[NW1];

__device__ __forceinline__ uint32_t smem_u32(const void* p) {
    uint32_t a;
    asm("{ .reg .u64 t; cvta.to.shared.u64 t, %1; cvt.u32.u64 %0, t; }" : "=r"(a) : "l"(p));
    return a;
}
__device__ __forceinline__ void ldsm_x4(uint32_t* r, uint32_t addr) {
    asm volatile("ldmatrix.sync.aligned.m8n8.x4.shared.b16 {%0,%1,%2,%3}, [%4];"
        : "=r"(r[0]), "=r"(r[1]), "=r"(r[2]), "=r"(r[3]) : "r"(addr));
}
__device__ __forceinline__ void mma_bf16(float* c, const uint32_t* a, const uint32_t* b) {
    asm volatile("mma.sync.aligned.m16n8k16.row.col.f32.bf16.bf16.f32 "
        "{%0,%1,%2,%3}, {%4,%5,%6,%7}, {%8,%9}, {%0,%1,%2,%3};"
        : "+f"(c[0]), "+f"(c[1]), "+f"(c[2]), "+f"(c[3])
        : "r"(a[0]), "r"(a[1]), "r"(a[2]), "r"(a[3]), "r"(b[0]), "r"(b[1]));
}
__device__ __forceinline__ void split2(float v0, float v1, uint32_t& hw, uint32_t& lw) {
    __nv_bfloat16 h0 = __float2bfloat16(v0), h1 = __float2bfloat16(v1);
    __nv_bfloat16 l0 = __float2bfloat16(v0 - __bfloat162float(h0));
    __nv_bfloat16 l1 = __float2bfloat16(v1 - __bfloat162float(h1));
    hw = (uint32_t)__bfloat16_as_ushort(h0) | ((uint32_t)__bfloat16_as_ushort(h1) << 16);
    lw = (uint32_t)__bfloat16_as_ushort(l0) | ((uint32_t)__bfloat16_as_ushort(l1) << 16);
}

// ---- prep: split W to bf16 hi/lo AND permute into fragment order -------------
__global__ __launch_bounds__(256) void prep_kernel(const float* __restrict__ W0,
                                                   const float* __restrict__ W1) {
    int i = blockIdx.x * 256 + threadIdx.x;
    if (i < NW0) {
        int l = i & 31, r = (i >> 5) & 1, tt = (i >> 6) & 3, w = (i >> 8) & 3, ks = i >> 10;
        int nr = w*32 + tt*8 + (l >> 2);
        int k  = ks*16 + (l & 3)*2 + r*8;
        split2(W0[nr*192 + k], W0[nr*192 + k + 1], g_pw0h[i], g_pw0l[i]);
    } else if (i < NW0 + NW1) {
        int j = i - NW0;
        int l = j & 31, r = (j >> 5) & 1, tt = (j >> 6) & 3, w = (j >> 8) & 3, ks = j >> 10;
        int nr = w*32 + tt*8 + (l >> 2);
        int k  = ks*16 + (l & 3)*2 + r*8;
        split2(W1[nr*128 + k], W1[nr*128 + k + 1], g_pw1h[j], g_pw1l[j]);
    }
}

// smem byte offsets (16B aligned); sRed aliases XH (dead after phase A)
#define OFF_XH   0            // 32*400   = 12800
#define OFF_XL   12800        // 12800
#define OFF_Y2H  25600        // 32*272   = 8704
#define OFF_Y2L  34304        // 8704
#define OFF_SY   43008        // 24*128*4 = 12288
#define OFF_SA   55296        // 528*4    = 2112
#define SMEM_BYTES 57408      // 4 blocks/SM (233472/57408 = 4.07)

__global__ __launch_bounds__(128) void fused_kernel(
    const float* __restrict__ x,  const float* __restrict__ A,
    const float* __restrict__ b0, const float* __restrict__ b1,
    float* __restrict__ out)
{
    extern __shared__ char sm[];
    float* sY   = reinterpret_cast<float*>(sm + OFF_SY);
    float* sA   = reinterpret_cast<float*>(sm + OFF_SA);
    float* sRed = reinterpret_cast<float*>(sm + OFF_XH);   // aliases dead XH
    const uint32_t sbase = smem_u32(sm);

    const int bt = blockIdx.x, t = threadIdx.x;
    const int wid = t >> 5, l = t & 31;
    const int n0 = wid * 32;
    const int h0 = ((wid & 1) << 5) + l, h1 = h0 + 64;
    const int chalf = wid >> 1, cbase = chalf * 11;

    // ---- Stage: x -> bf16 hi/lo (rows 0..21), A -> sA, zero sY pad rows ----
    {
        const float* xr = x + (size_t)bt * (22*192);
        for (int i = t; i < 22*24; i += 128) {
            int row = i / 24, cr = i - row * 24;
            const float4* g4 = reinterpret_cast<const float4*>(xr + row*192 + cr*8);
            float4 a = g4[0], b = g4[1];
            uint32_t hw[4], lw[4];
            split2(a.x, a.y, hw[0], lw[0]); split2(a.z, a.w, hw[1], lw[1]);
            split2(b.x, b.y, hw[2], lw[2]); split2(b.z, b.w, hw[3], lw[3]);
            *reinterpret_cast<uint4*>(sm + OFF_XH + row*400 + cr*16) =
                make_uint4(hw[0], hw[1], hw[2], hw[3]);
            *reinterpret_cast<uint4*>(sm + OFF_XL + row*400 + cr*16) =
                make_uint4(lw[0], lw[1], lw[2], lw[3]);
        }
        const float* Ag = A + (size_t)bt * 484;
        for (int i = t; i < 484; i += 128) { int c = i / 22; sA[c*24 + (i - c*22)] = Ag[i]; }
        if (t < 44) sA[(t >> 1)*24 + 22 + (t & 1)] = 0.f;
        sY[22*128 + t] = 0.f;
        sY[23*128 + t] = 0.f;
    }
    __syncthreads();

    float acc[2][4][4];
    const int aoff  = (l & 15) * 400 + (l >> 4) * 16;
    const int aoff2 = (l & 15) * 272 + (l >> 4) * 16;

    // ==== Phase A: y = x @ W0^T  (K=192, 12 k-steps) ====
    #pragma unroll
    for (int mi = 0; mi < 2; mi++)
        #pragma unroll
        for (int tt = 0; tt < 4; tt++)
            #pragma unroll
            for (int q = 0; q < 4; q++) acc[mi][tt][q] = 0.f;

    for (int ks = 0; ks < 12; ks++) {
        uint32_t ah[2][4], al[2][4], bh[4][2], bl[4][2];
        ldsm_x4(ah[0], sbase + OFF_XH + ks*32 + aoff);
        ldsm_x4(ah[1], sbase + OFF_XH + 16*400 + ks*32 + aoff);
        ldsm_x4(al[0], sbase + OFF_XL + ks*32 + aoff);
        ldsm_x4(al[1], sbase + OFF_XL + 16*400 + ks*32 + aoff);
        const uint32_t* pH = g_pw0h + ((ks*4 + wid)*4)*64 + l;   // tt stride 64, r stride 32
        const uint32_t* pL = g_pw0l + ((ks*4 + wid)*4)*64 + l;
        #pragma unroll
        for (int tt = 0; tt < 4; tt++) {
            bh[tt][0] = pH[tt*64];  bh[tt][1] = pH[tt*64 + 32];
            bl[tt][0] = pL[tt*64];  bl[tt][1] = pL[tt*64 + 32];
        }
        #pragma unroll
        for (int mi = 0; mi < 2; mi++)
            #pragma unroll
            for (int tt = 0; tt < 4; tt++) mma_bf16(acc[mi][tt], ah[mi], bh[tt]);
        #pragma unroll
        for (int mi = 0; mi < 2; mi++)
            #pragma unroll
            for (int tt = 0; tt < 4; tt++) mma_bf16(acc[mi][tt], al[mi], bh[tt]);
        #pragma unroll
        for (int mi = 0; mi < 2; mi++)
            #pragma unroll
            for (int tt = 0; tt < 4; tt++) mma_bf16(acc[mi][tt], ah[mi], bl[tt]);
    }
    #pragma unroll
    for (int mi = 0; mi < 2; mi++)
        #pragma unroll
        for (int tt = 0; tt < 4; tt++) {
            int r0 = mi*16 + (l >> 2), c = n0 + tt*8 + (l & 3)*2;
            if (r0 < 22)
                *reinterpret_cast<float2*>(sY + r0*128 + c) =
                    make_float2(acc[mi][tt][0], acc[mi][tt][1]);
            if (r0 + 8 < 22)
                *reinterpret_cast<float2*>(sY + (r0+8)*128 + c) =
                    make_float2(acc[mi][tt][2], acc[mi][tt][3]);
        }
    __syncthreads();

    // ==== Phase B: y2 = relu(b0 + A@y) -> bf16 hi/lo ====
    {
        float a0[11], a1[11];
        const float bb0 = b0[h0], bb1 = b0[h1];
        #pragma unroll
        for (int c = 0; c < 11; c++) { a0[c] = bb0; a1[c] = bb1; }
        const float4* sA4 = reinterpret_cast<const float4*>(sA);
        #pragma unroll
        for (int jg = 0; jg < 6; jg++) {
            float yv0[4], yv1[4];
            #pragma unroll
            for (int q = 0; q < 4; q++) {
                yv0[q] = sY[(jg*4+q)*128 + h0];
                yv1[q] = sY[(jg*4+q)*128 + h1];
            }
            #pragma unroll
            for (int c = 0; c < 11; c++) {
                float4 av = sA4[(cbase + c)*6 + jg];
                a0[c] += av.x*yv0[0] + av.y*yv0[1] + av.z*yv0[2] + av.w*yv0[3];
                a1[c] += av.x*yv1[0] + av.y*yv1[1] + av.z*yv1[2] + av.w*yv1[3];
            }
        }
        __nv_bfloat16* y2h = reinterpret_cast<__nv_bfloat16*>(sm + OFF_Y2H);
        __nv_bfloat16* y2l = reinterpret_cast<__nv_bfloat16*>(sm + OFF_Y2L);
        #pragma unroll
        for (int c = 0; c < 11; c++) {
            float v0 = fmaxf(a0[c], 0.f), v1 = fmaxf(a1[c], 0.f);
            __nv_bfloat16 hh0 = __float2bfloat16(v0), hh1 = __float2bfloat16(v1);
            y2h[(cbase+c)*Y2S + h0] = hh0;
            y2l[(cbase+c)*Y2S + h0] = __float2bfloat16(v0 - __bfloat162float(hh0));
            y2h[(cbase+c)*Y2S + h1] = hh1;
            y2l[(cbase+c)*Y2S + h1] = __float2bfloat16(v1 - __bfloat162float(hh1));
        }
    }
    __syncthreads();

    // ==== Phase C: y3 = y2 @ W1^T  (K=128, 8 k-steps) ====
    #pragma unroll
    for (int mi = 0; mi < 2; mi++)
        #pragma unroll
        for (int tt = 0; tt < 4; tt++)
            #pragma unroll
            for (int q = 0; q < 4; q++) acc[mi][tt][q] = 0.f;

    for (int ks = 0; ks < 8; ks++) {
        uint32_t ah[2][4], al[2][4], bh[4][2], bl[4][2];
        ldsm_x4(ah[0], sbase + OFF_Y2H + ks*32 + aoff2);
        ldsm_x4(ah[1], sbase + OFF_Y2H + 16*272 + ks*32 + aoff2);
        ldsm_x4(al[0], sbase + OFF_Y2L + ks*32 + aoff2);
        ldsm_x4(al[1], sbase + OFF_Y2L + 16*272 + ks*32 + aoff2);
        const uint32_t* pH = g_pw1h + ((ks*4 + wid)*4)*64 + l;
        const uint32_t* pL = g_pw1l + ((ks*4 + wid)*4)*64 + l;
        #pragma unroll
        for (int tt = 0; tt < 4; tt++) {
            bh[tt][0] = pH[tt*64];  bh[tt][1] = pH[tt*64 + 32];
            bl[tt][0] = pL[tt*64];  bl[tt][1] = pL[tt*64 + 32];
        }
        #pragma unroll
        for (int mi = 0; mi < 2; mi++)
            #pragma unroll
            for (int tt = 0; tt < 4; tt++) mma_bf16(acc[mi][tt], ah[mi], bh[tt]);
        #pragma unroll
        for (int mi = 0; mi < 2; mi++)
            #pragma unroll
            for (int tt = 0; tt < 4; tt++) mma_bf16(acc[mi][tt], al[mi], bh[tt]);
        #pragma unroll
        for (int mi = 0; mi < 2; mi++)
            #pragma unroll
            for (int tt = 0; tt < 4; tt++) mma_bf16(acc[mi][tt], ah[mi], bl[tt]);
    }
    #pragma unroll
    for (int mi = 0; mi < 2; mi++)
        #pragma unroll
        for (int tt = 0; tt < 4; tt++) {
            int r0 = mi*16 + (l >> 2), c = n0 + tt*8 + (l & 3)*2;
            if (r0 < 22)
                *reinterpret_cast<float2*>(sY + r0*128 + c) =
                    make_float2(acc[mi][tt][0], acc[mi][tt][1]);
            if (r0 + 8 < 22)
                *reinterpret_cast<float2*>(sY + (r0+8)*128 + c) =
                    make_float2(acc[mi][tt][2], acc[mi][tt][3]);
        }
    __syncthreads();

    // ==== Phase D: out = mean_c relu(b1 + A@y3) ====
    {
        float a0[11], a1[11];
        const float bb0 = b1[h0], bb1 = b1[h1];
        #pragma unroll
        for (int c = 0; c < 11; c++) { a0[c] = bb0; a1[c] = bb1; }
        const float4* sA4 = reinterpret_cast<const float4*>(sA);
        #pragma unroll
        for (int jg = 0; jg < 6; jg++) {
            float yv0[4], yv1[4];
            #pragma unroll
            for (int q = 0; q < 4; q++) {
                yv0[q] = sY[(jg*4+q)*128 + h0];
                yv1[q] = sY[(jg*4+q)*128 + h1];
            }
            #pragma unroll
            for (int c = 0; c < 11; c++) {
                float4 av = sA4[(cbase + c)*6 + jg];
                a0[c] += av.x*yv0[0] + av.y*yv0[1] + av.z*yv0[2] + av.w*yv0[3];
                a1[c] += av.x*yv1[0] + av.y*yv1[1] + av.z*yv1[2] + av.w*yv1[3];
            }
        }
        float p0 = 0.f, p1 = 0.f;
        #pragma unroll
        for (int c = 0; c < 11; c++) { p0 += fmaxf(a0[c], 0.f); p1 += fmaxf(a1[c], 0.f); }
        sRed[chalf*128 + h0] = p0;
        sRed[chalf*128 + h1] = p1;
        __syncthreads();
        if (t < 64) {
            out[(size_t)bt*128 + h0] = (sRed[h0] + sRed[128 + h0]) * (1.f/22.f);
            out[(size_t)bt*128 + h1] = (sRed[h1] + sRed[128 + h1]) * (1.f/22.f);
        }
    }
}

extern "C" void kernel_launch(void* const* d_in, const int* in_sizes, int n_in,
                              void* d_out, int out_size) {
    const float* x  = (const float*)d_in[0];   // [32,512,22,192]
    const float* A  = (const float*)d_in[1];   // [16384,22,22]
    const float* W0 = (const float*)d_in[2];   // [128,192]
    const float* b0 = (const float*)d_in[3];
    const float* W1 = (const float*)d_in[4];   // [128,128]
    const float* b1 = (const float*)d_in[5];
    float* out = (float*)d_out;                // [16384,128]

    cudaFuncSetAttribute(fused_kernel, cudaFuncAttributeMaxDynamicSharedMemorySize, SMEM_BYTES);
    prep_kernel<<<(NW0 + NW1 + 255) / 256, 256>>>(W0, W1);
    fused_kernel<<<NBT, 128, SMEM_BYTES>>>(x, A, b0, b1, out);
}

// round 10
// speedup vs baseline: 5.0695x; 1.4391x over previous
#include <cuda_runtime.h>
#include <cuda_bf16.h>
#include <cstdint>

// TemporalGCN  B=32,T=512,C=22,FREQ=192,HID=128 — 2 (b,t) per block.
// M=44 (22+22) packed in a 48-row mma tile (rows 0-21 bt0, 24-45 bt1).
// Phases A/C: mma.sync bf16x3 split, W pre-permuted to fragment order.

#define NBT   16384
#define NBLK  8192
#define Y2S   136      // bf16 elems per Y2 row (272B, ldmatrix conflict-free)

#define NW0  (12*4*4*2*32)
#define NW1  (8*4*4*2*32)
__device__ uint32_t g_pw0h[NW0], g_pw0l[NW0];
__device__ uint32_t g_pw1h[NW1], g_pw1l[NW1];

__device__ __forceinline__ uint32_t smem_u32(const void* p) {
    uint32_t a;
    asm("{ .reg .u64 t; cvta.to.shared.u64 t, %1; cvt.u32.u64 %0, t; }" : "=r"(a) : "l"(p));
    return a;
}
__device__ __forceinline__ void ldsm_x4(uint32_t* r, uint32_t addr) {
    asm volatile("ldmatrix.sync.aligned.m8n8.x4.shared.b16 {%0,%1,%2,%3}, [%4];"
        : "=r"(r[0]), "=r"(r[1]), "=r"(r[2]), "=r"(r[3]) : "r"(addr));
}
__device__ __forceinline__ void mma_bf16(float* c, const uint32_t* a, const uint32_t* b) {
    asm volatile("mma.sync.aligned.m16n8k16.row.col.f32.bf16.bf16.f32 "
        "{%0,%1,%2,%3}, {%4,%5,%6,%7}, {%8,%9}, {%0,%1,%2,%3};"
        : "+f"(c[0]), "+f"(c[1]), "+f"(c[2]), "+f"(c[3])
        : "r"(a[0]), "r"(a[1]), "r"(a[2]), "r"(a[3]), "r"(b[0]), "r"(b[1]));
}
__device__ __forceinline__ void split2(float v0, float v1, uint32_t& hw, uint32_t& lw) {
    __nv_bfloat16 h0 = __float2bfloat16(v0), h1 = __float2bfloat16(v1);
    __nv_bfloat16 l0 = __float2bfloat16(v0 - __bfloat162float(h0));
    __nv_bfloat16 l1 = __float2bfloat16(v1 - __bfloat162float(h1));
    hw = (uint32_t)__bfloat16_as_ushort(h0) | ((uint32_t)__bfloat16_as_ushort(h1) << 16);
    lw = (uint32_t)__bfloat16_as_ushort(l0) | ((uint32_t)__bfloat16_as_ushort(l1) << 16);
}

__global__ __launch_bounds__(256) void prep_kernel(const float* __restrict__ W0,
                                                   const float* __restrict__ W1) {
    int i = blockIdx.x * 256 + threadIdx.x;
    if (i < NW0) {
        int l = i & 31, r = (i >> 5) & 1, tt = (i >> 6) & 3, w = (i >> 8) & 3, ks = i >> 10;
        int nr = w*32 + tt*8 + (l >> 2);
        int k  = ks*16 + (l & 3)*2 + r*8;
        split2(W0[nr*192 + k], W0[nr*192 + k + 1], g_pw0h[i], g_pw0l[i]);
    } else if (i < NW0 + NW1) {
        int j = i - NW0;
        int l = j & 31, r = (j >> 5) & 1, tt = (j >> 6) & 3, w = (j >> 8) & 3, ks = j >> 10;
        int nr = w*32 + tt*8 + (l >> 2);
        int k  = ks*16 + (l & 3)*2 + r*8;
        split2(W1[nr*128 + k], W1[nr*128 + k + 1], g_pw1h[j], g_pw1l[j]);
    }
}

// smem: XH 48*400 | XL 48*400 | Y2H 48*272 | Y2L 48*272 | sA 2*528*4
// sY (48*128*4 = 24576B) aliases XH/XL (dead after phase A, barrier-protected)
// sRed (512*4 = 2048B) aliases Y2H (dead after phase C)
#define OFF_XH   0
#define OFF_XL   19200
#define OFF_Y2H  38400
#define OFF_Y2L  51456
#define OFF_SA   64512
#define SMEM_BYTES 68736      // 3 blocks/SM

__global__ __launch_bounds__(128, 3) void fused_kernel(
    const float* __restrict__ x,  const float* __restrict__ A,
    const float* __restrict__ b0, const float* __restrict__ b1,
    float* __restrict__ out)
{
    extern __shared__ char sm[];
    float* sY   = reinterpret_cast<float*>(sm + OFF_XH);    // aliases XH/XL
    float* sA   = reinterpret_cast<float*>(sm + OFF_SA);
    float* sRed = reinterpret_cast<float*>(sm + OFF_Y2H);   // aliases Y2H
    const uint32_t sbase = smem_u32(sm);

    const int bt0 = blockIdx.x * 2;
    const int t = threadIdx.x;
    const int wid = t >> 5, l = t & 31;
    const int n0 = wid * 32;
    const int h0 = ((wid & 1) << 5) + l, h1 = h0 + 64;
    const int chalf = wid >> 1, cbase = chalf * 11;

    // ---- Stage: 44 contiguous x rows -> bf16 hi/lo (smem rows 0-21, 24-45); A ----
    {
        const float* xr = x + (size_t)bt0 * (22*192);        // bt0,bt1 rows contiguous
        for (int i = t; i < 44*24; i += 128) {
            int row = i / 24, cr = i - row * 24;
            int srow = (row < 22) ? row : row + 2;
            const float4* g4 = reinterpret_cast<const float4*>(xr + row*192 + cr*8);
            float4 a = g4[0], b = g4[1];
            uint32_t hw[4], lw[4];
            split2(a.x, a.y, hw[0], lw[0]); split2(a.z, a.w, hw[1], lw[1]);
            split2(b.x, b.y, hw[2], lw[2]); split2(b.z, b.w, hw[3], lw[3]);
            *reinterpret_cast<uint4*>(sm + OFF_XH + srow*400 + cr*16) =
                make_uint4(hw[0], hw[1], hw[2], hw[3]);
            *reinterpret_cast<uint4*>(sm + OFF_XL + srow*400 + cr*16) =
                make_uint4(lw[0], lw[1], lw[2], lw[3]);
        }
        const float* Ag = A + (size_t)bt0 * 484;             // 2*484 contiguous
        for (int i = t; i < 968; i += 128) {
            int btl = i / 484, rem = i - btl*484;
            int c = rem / 22, j = rem - c*22;
            sA[btl*528 + c*24 + j] = Ag[i];
        }
        if (t < 88) {                                        // zero sA pad cols
            int btl = t / 44, rr = (t % 44) >> 1;
            sA[btl*528 + rr*24 + 22 + (t & 1)] = 0.f;
        }
    }
    __syncthreads();

    float acc[3][4][4];
    const int aoff  = (l & 15) * 400 + (l >> 4) * 16;
    const int aoff2 = (l & 15) * 272 + (l >> 4) * 16;

    // ==== Phase A: y = x @ W0^T  (M=48 tile, K=192) ====
    #pragma unroll
    for (int mi = 0; mi < 3; mi++)
        #pragma unroll
        for (int tt = 0; tt < 4; tt++)
            #pragma unroll
            for (int q = 0; q < 4; q++) acc[mi][tt][q] = 0.f;

    for (int ks = 0; ks < 12; ks++) {
        uint32_t ah[3][4], al[3][4], bh[4][2], bl[4][2];
        #pragma unroll
        for (int mi = 0; mi < 3; mi++) {
            ldsm_x4(ah[mi], sbase + OFF_XH + mi*16*400 + ks*32 + aoff);
            ldsm_x4(al[mi], sbase + OFF_XL + mi*16*400 + ks*32 + aoff);
        }
        const uint32_t* pH = g_pw0h + ((ks*4 + wid)*4)*64 + l;
        const uint32_t* pL = g_pw0l + ((ks*4 + wid)*4)*64 + l;
        #pragma unroll
        for (int tt = 0; tt < 4; tt++) {
            bh[tt][0] = pH[tt*64];  bh[tt][1] = pH[tt*64 + 32];
            bl[tt][0] = pL[tt*64];  bl[tt][1] = pL[tt*64 + 32];
        }
        #pragma unroll
        for (int mi = 0; mi < 3; mi++)
            #pragma unroll
            for (int tt = 0; tt < 4; tt++) mma_bf16(acc[mi][tt], ah[mi], bh[tt]);
        #pragma unroll
        for (int mi = 0; mi < 3; mi++)
            #pragma unroll
            for (int tt = 0; tt < 4; tt++) mma_bf16(acc[mi][tt], al[mi], bh[tt]);
        #pragma unroll
        for (int mi = 0; mi < 3; mi++)
            #pragma unroll
            for (int tt = 0; tt < 4; tt++) mma_bf16(acc[mi][tt], ah[mi], bl[tt]);
    }
    __syncthreads();    // all XH/XL ldsm done before sY overwrites the region

    #pragma unroll
    for (int mi = 0; mi < 3; mi++)
        #pragma unroll
        for (int tt = 0; tt < 4; tt++) {
            int r0 = mi*16 + (l >> 2), c = n0 + tt*8 + (l & 3)*2;
            if (r0 < 22 || (r0 >= 24 && r0 < 46))
                *reinterpret_cast<float2*>(sY + r0*128 + c) =
                    make_float2(acc[mi][tt][0], acc[mi][tt][1]);
            int r1 = r0 + 8;
            if (r1 < 22 || (r1 >= 24 && r1 < 46))
                *reinterpret_cast<float2*>(sY + r1*128 + c) =
                    make_float2(acc[mi][tt][2], acc[mi][tt][3]);
        }
    {   // zero sY pad rows 22,23,46,47 (read by mixes)
        sY[22*128 + t] = 0.f;  sY[23*128 + t] = 0.f;
        sY[46*128 + t] = 0.f;  sY[47*128 + t] = 0.f;
    }
    __syncthreads();

    // ==== Phase B: y2 = relu(b0 + A@y) -> bf16 hi/lo (both bt) ====
    {
        const float bb0 = b0[h0], bb1 = b0[h1];
        __nv_bfloat16* y2h = reinterpret_cast<__nv_bfloat16*>(sm + OFF_Y2H);
        __nv_bfloat16* y2l = reinterpret_cast<__nv_bfloat16*>(sm + OFF_Y2L);
        #pragma unroll
        for (int btl = 0; btl < 2; btl++) {
            const float* sYb = sY + btl*24*128;
            const float4* sA4 = reinterpret_cast<const float4*>(sA + btl*528);
            float a0[11], a1[11];
            #pragma unroll
            for (int c = 0; c < 11; c++) { a0[c] = bb0; a1[c] = bb1; }
            #pragma unroll
            for (int jg = 0; jg < 6; jg++) {
                float yv0[4], yv1[4];
                #pragma unroll
                for (int q = 0; q < 4; q++) {
                    yv0[q] = sYb[(jg*4+q)*128 + h0];
                    yv1[q] = sYb[(jg*4+q)*128 + h1];
                }
                #pragma unroll
                for (int c = 0; c < 11; c++) {
                    float4 av = sA4[(cbase + c)*6 + jg];
                    a0[c] += av.x*yv0[0] + av.y*yv0[1] + av.z*yv0[2] + av.w*yv0[3];
                    a1[c] += av.x*yv1[0] + av.y*yv1[1] + av.z*yv1[2] + av.w*yv1[3];
                }
            }
            #pragma unroll
            for (int c = 0; c < 11; c++) {
                int row = btl*24 + cbase + c;
                float v0 = fmaxf(a0[c], 0.f), v1 = fmaxf(a1[c], 0.f);
                __nv_bfloat16 hh0 = __float2bfloat16(v0), hh1 = __float2bfloat16(v1);
                y2h[row*Y2S + h0] = hh0;
                y2l[row*Y2S + h0] = __float2bfloat16(v0 - __bfloat162float(hh0));
                y2h[row*Y2S + h1] = hh1;
                y2l[row*Y2S + h1] = __float2bfloat16(v1 - __bfloat162float(hh1));
            }
        }
    }
    __syncthreads();

    // ==== Phase C: y3 = y2 @ W1^T  (M=48 tile, K=128) ====
    #pragma unroll
    for (int mi = 0; mi < 3; mi++)
        #pragma unroll
        for (int tt = 0; tt < 4; tt++)
            #pragma unroll
            for (int q = 0; q < 4; q++) acc[mi][tt][q] = 0.f;

    for (int ks = 0; ks < 8; ks++) {
        uint32_t ah[3][4], al[3][4], bh[4][2], bl[4][2];
        #pragma unroll
        for (int mi = 0; mi < 3; mi++) {
            ldsm_x4(ah[mi], sbase + OFF_Y2H + mi*16*272 + ks*32 + aoff2);
            ldsm_x4(al[mi], sbase + OFF_Y2L + mi*16*272 + ks*32 + aoff2);
        }
        const uint32_t* pH = g_pw1h + ((ks*4 + wid)*4)*64 + l;
        const uint32_t* pL = g_pw1l + ((ks*4 + wid)*4)*64 + l;
        #pragma unroll
        for (int tt = 0; tt < 4; tt++) {
            bh[tt][0] = pH[tt*64];  bh[tt][1] = pH[tt*64 + 32];
            bl[tt][0] = pL[tt*64];  bl[tt][1] = pL[tt*64 + 32];
        }
        #pragma unroll
        for (int mi = 0; mi < 3; mi++)
            #pragma unroll
            for (int tt = 0; tt < 4; tt++) mma_bf16(acc[mi][tt], ah[mi], bh[tt]);
        #pragma unroll
        for (int mi = 0; mi < 3; mi++)
            #pragma unroll
            for (int tt = 0; tt < 4; tt++) mma_bf16(acc[mi][tt], al[mi], bh[tt]);
        #pragma unroll
        for (int mi = 0; mi < 3; mi++)
            #pragma unroll
            for (int tt = 0; tt < 4; tt++) mma_bf16(acc[mi][tt], ah[mi], bl[tt]);
    }
    // sY region (XH) dead since phase B; Y2 reads are per-warp-complete: epilogue safe
    #pragma unroll
    for (int mi = 0; mi < 3; mi++)
        #pragma unroll
        for (int tt = 0; tt < 4; tt++) {
            int r0 = mi*16 + (l >> 2), c = n0 + tt*8 + (l & 3)*2;
            if (r0 < 22 || (r0 >= 24 && r0 < 46))
                *reinterpret_cast<float2*>(sY + r0*128 + c) =
                    make_float2(acc[mi][tt][0], acc[mi][tt][1]);
            int r1 = r0 + 8;
            if (r1 < 22 || (r1 >= 24 && r1 < 46))
                *reinterpret_cast<float2*>(sY + r1*128 + c) =
                    make_float2(acc[mi][tt][2], acc[mi][tt][3]);
        }
    __syncthreads();

    // ==== Phase D: out = mean_c relu(b1 + A@y3) (both bt) ====
    {
        const float bb0 = b1[h0], bb1 = b1[h1];
        #pragma unroll
        for (int btl = 0; btl < 2; btl++) {
            const float* sYb = sY + btl*24*128;
            const float4* sA4 = reinterpret_cast<const float4*>(sA + btl*528);
            float a0[11], a1[11];
            #pragma unroll
            for (int c = 0; c < 11; c++) { a0[c] = bb0; a1[c] = bb1; }
            #pragma unroll
            for (int jg = 0; jg < 6; jg++) {
                float yv0[4], yv1[4];
                #pragma unroll
                for (int q = 0; q < 4; q++) {
                    yv0[q] = sYb[(jg*4+q)*128 + h0];
                    yv1[q] = sYb[(jg*4+q)*128 + h1];
                }
                #pragma unroll
                for (int c = 0; c < 11; c++) {
                    float4 av = sA4[(cbase + c)*6 + jg];
                    a0[c] += av.x*yv0[0] + av.y*yv0[1] + av.z*yv0[2] + av.w*yv0[3];
                    a1[c] += av.x*yv1[0] + av.y*yv1[1] + av.z*yv1[2] + av.w*yv1[3];
                }
            }
            float p0 = 0.f, p1 = 0.f;
            #pragma unroll
            for (int c = 0; c < 11; c++) { p0 += fmaxf(a0[c], 0.f); p1 += fmaxf(a1[c], 0.f); }
            sRed[btl*256 + chalf*128 + h0] = p0;
            sRed[btl*256 + chalf*128 + h1] = p1;
        }
        __syncthreads();
        out[(size_t)bt0*128 + t]       = (sRed[t]       + sRed[128 + t]) * (1.f/22.f);
        out[(size_t)(bt0+1)*128 + t]   = (sRed[256 + t] + sRed[384 + t]) * (1.f/22.f);
    }
}

extern "C" void kernel_launch(void* const* d_in, const int* in_sizes, int n_in,
                              void* d_out, int out_size) {
    const float* x  = (const float*)d_in[0];   // [32,512,22,192]
    const float* A  = (const float*)d_in[1];   // [16384,22,22]
    const float* W0 = (const float*)d_in[2];   // [128,192]
    const float* b0 = (const float*)d_in[3];
    const float* W1 = (const float*)d_in[4];   // [128,128]
    const float* b1 = (const float*)d_in[5];
    float* out = (float*)d_out;                // [16384,128]

    cudaFuncSetAttribute(fused_kernel, cudaFuncAttributeMaxDynamicSharedMemorySize, SMEM_BYTES);
    prep_kernel<<<(NW0 + NW1 + 255) / 256, 256>>>(W0, W1);
    fused_kernel<<<NBLK, 128, SMEM_BYTES>>>(x, A, b0, b1, out);
}